// round 12
// baseline (speedup 1.0000x reference)
#include <cuda_runtime.h>

#define BATCH 256
#define SEQ   512
#define DIM   7
#define THREADS 128
#define RPT     2            // rows per thread (phase A)
#define ROWS_CTA 64          // rows covered per CTA (1/8 batch)

typedef unsigned long long u64;

// ---------- packed f32x2 helpers (Blackwell-only, PTX required) ----------
__device__ __forceinline__ u64 pk2(float a, float b) {
    u64 r;
    asm("mov.b64 %0, {%1, %2};" : "=l"(r) : "f"(a), "f"(b));
    return r;
}
__device__ __forceinline__ void upk2(u64 v, float& a, float& b) {
    asm("mov.b64 {%0, %1}, %2;" : "=f"(a), "=f"(b) : "l"(v));
}
__device__ __forceinline__ u64 fma2_(u64 a, u64 b, u64 c) {
    u64 d;
    asm("fma.rn.f32x2 %0, %1, %2, %3;" : "=l"(d) : "l"(a), "l"(b), "l"(c));
    return d;
}
__device__ __forceinline__ u64 mul2_(u64 a, u64 b) {
    u64 d;
    asm("mul.rn.f32x2 %0, %1, %2;" : "=l"(d) : "l"(a), "l"(b));
    return d;
}
__device__ __forceinline__ u64 add2_(u64 a, u64 b) {
    u64 d;
    asm("add.rn.f32x2 %0, %1, %2;" : "=l"(d) : "l"(a), "l"(b));
    return d;
}
__device__ __forceinline__ float ex2f(float x) {
    float y; asm("ex2.approx.f32 %0, %1;" : "=f"(y) : "f"(x)); return y;
}
__device__ __forceinline__ float lg2f(float x) {
    float y; asm("lg2.approx.f32 %0, %1;" : "=f"(y) : "f"(x)); return y;
}
__device__ __forceinline__ float rcpf(float x) {
    float y; asm("rcp.approx.f32 %0, %1;" : "=f"(y) : "f"(x)); return y;
}

// ---------- Single fused kernel ----------
__global__ __launch_bounds__(THREADS, 5) void attn_kernel(
    const float* __restrict__ feat,
    const float* __restrict__ Wm,
    const float* __restrict__ bia,
    const float* __restrict__ abias,
    const float* __restrict__ gamma,
    const float* __restrict__ beta,
    float* __restrict__ outA, float* __restrict__ outW) {
    __shared__ float4 sP[SEQ * 2];          // 16 KB (pre-scaled projected, pad 0)
    __shared__ float4 sV[SEQ * 2];          // 16 KB (biased values, pad 1.0 -> row sums)
    __shared__ u64    part[3][ROWS_CTA][4]; // 6 KB  (t-quarter partials, warps 1..3)
    __shared__ float  slinv[ROWS_CTA];      // -log2(rowsum)

    const int b    = blockIdx.y;
    const int oct  = blockIdx.x;            // 0..7 -> which 64 rows
    const int tid  = threadIdx.x;
    const int lane = tid & 31;
    const int warp = tid >> 5;              // 0..3 = t-quarter owner

    // ---- Fused prep/staging: read features, project, scale, fill smem ----
    {
        const float SC = 0.7384116545f;     // sqrt(log2(e)/sqrt(7))
        float wr[7][7], br[7], ar[7];
#pragma unroll
        for (int e = 0; e < 7; e++) {
            br[e] = __ldg(&bia[e]);
            ar[e] = __ldg(&abias[e]);
#pragma unroll
            for (int d = 0; d < 7; d++) wr[e][d] = __ldg(&Wm[e * 7 + d]);
        }
#pragma unroll
        for (int i = 0; i < 4; i++) {
            const int r = tid + i * THREADS;            // 0..511
            const float* fp = feat + ((size_t)b * SEQ + r) * 7;
            float f[7];
#pragma unroll
            for (int d = 0; d < 7; d++) f[d] = fp[d] + ar[d];
            float p[7];
#pragma unroll
            for (int e = 0; e < 7; e++) {
                float s = br[e];
#pragma unroll
                for (int d = 0; d < 7; d++) s = fmaf(f[d], wr[e][d], s);
                p[e] = s * SC;
            }
            sV[r * 2 + 0] = make_float4(f[0], f[1], f[2], f[3]);
            sV[r * 2 + 1] = make_float4(f[4], f[5], f[6], 1.0f);  // pad=1 -> sum slot
            sP[r * 2 + 0] = make_float4(p[0], p[1], p[2], p[3]);
            sP[r * 2 + 1] = make_float4(p[4], p[5], p[6], 0.f);
        }
    }
    __syncthreads();

    // Direct 64-bit pair views of the tables (LDS.128 -> f32x2 operands).
    const ulonglong2* sPu = reinterpret_cast<const ulonglong2*>(sP);
    const ulonglong2* sVu = reinterpret_cast<const ulonglong2*>(sV);

    const int rbase = oct * ROWS_CTA;                   // CTA row offset in batch

    // Every warp covers the SAME 64 rows (slot s -> row lane + s*32), one t-quarter.
    u64 q[RPT][4];
#pragma unroll
    for (int s = 0; s < RPT; s++) {
        const int r = rbase + lane + s * 32;
        const ulonglong2 qa = sPu[r * 2 + 0];
        const ulonglong2 qb = sPu[r * 2 + 1];
        q[s][0] = qa.x; q[s][1] = qa.y; q[s][2] = qb.x; q[s][3] = qb.y;  // pad 0
    }

    // ---- Phase A (t-quarter): attended accumulators; row sum rides in acc[s][3].hi ----
    u64 acc[RPT][4];
#pragma unroll
    for (int s = 0; s < RPT; s++) {
#pragma unroll
        for (int j = 0; j < 4; j++) acc[s][j] = 0ull;
    }

    const int t0 = warp * 128;
#pragma unroll 8
    for (int ti = 0; ti < 128; ti++) {
        const int t = t0 + ti;
        const ulonglong2 pA = sPu[t * 2 + 0];
        const ulonglong2 pB = sPu[t * 2 + 1];
        const ulonglong2 vA = sVu[t * 2 + 0];
        const ulonglong2 vB = sVu[t * 2 + 1];   // vB.y hi = 1.0 (sum slot)
#pragma unroll
        for (int s = 0; s < RPT; s++) {
            u64 z2 = mul2_(q[s][0], pA.x);
            z2 = fma2_(q[s][1], pA.y, z2);
            z2 = fma2_(q[s][2], pB.x, z2);
            z2 = fma2_(q[s][3], pB.y, z2);
            float za, zb; upk2(z2, za, zb);
            const float e = ex2f(za + zb);
            const u64 ee = pk2(e, e);
            acc[s][0] = fma2_(ee, vA.x, acc[s][0]);
            acc[s][1] = fma2_(ee, vA.y, acc[s][1]);
            acc[s][2] = fma2_(ee, vB.x, acc[s][2]);
            acc[s][3] = fma2_(ee, vB.y, acc[s][3]);
        }
    }

    // ---- Merge t-quarters: warps 1..3 publish, warp 0 combines + finishes ----
    if (warp > 0) {
#pragma unroll
        for (int s = 0; s < RPT; s++) {
#pragma unroll
            for (int j = 0; j < 4; j++) part[warp - 1][s * 32 + lane][j] = acc[s][j];
        }
    }
    __syncthreads();

    if (warp == 0) {
        float sum[RPT];
#pragma unroll
        for (int s = 0; s < RPT; s++) {
#pragma unroll
            for (int j = 0; j < 4; j++) {
                u64 m = add2_(part[0][s * 32 + lane][j], part[1][s * 32 + lane][j]);
                m = add2_(m, part[2][s * 32 + lane][j]);
                acc[s][j] = add2_(acc[s][j], m);
            }
            float a6, sm; upk2(acc[s][3], a6, sm);
            sum[s] = sm;
            slinv[lane + s * 32] = -lg2f(sm);
        }

        // ---- Attended + LayerNorm (fully per-lane) ----
        if (outA) {
            float g0 = __ldg(&gamma[0]), g1 = __ldg(&gamma[1]), g2 = __ldg(&gamma[2]),
                  g3 = __ldg(&gamma[3]), g4 = __ldg(&gamma[4]), g5 = __ldg(&gamma[5]),
                  g6 = __ldg(&gamma[6]);
            float b0 = __ldg(&beta[0]), b1 = __ldg(&beta[1]), b2 = __ldg(&beta[2]),
                  b3 = __ldg(&beta[3]), b4 = __ldg(&beta[4]), b5 = __ldg(&beta[5]),
                  b6 = __ldg(&beta[6]);
#pragma unroll
            for (int s = 0; s < RPT; s++) {
                float a0, a1, a2, a3, a4, a5, a6, ax;
                upk2(acc[s][0], a0, a1);
                upk2(acc[s][1], a2, a3);
                upk2(acc[s][2], a4, a5);
                upk2(acc[s][3], a6, ax);
                float iv = rcpf(sum[s]);
                a0 *= iv; a1 *= iv; a2 *= iv; a3 *= iv; a4 *= iv; a5 *= iv; a6 *= iv;
                float mu = (a0 + a1 + a2 + a3 + a4 + a5 + a6) * (1.0f / 7.0f);
                float e0 = a0 - mu, e1 = a1 - mu, e2 = a2 - mu, e3 = a3 - mu;
                float e4 = a4 - mu, e5 = a5 - mu, e6 = a6 - mu;
                float var = (e0*e0 + e1*e1 + e2*e2 + e3*e3 + e4*e4 + e5*e5 + e6*e6) * (1.0f / 7.0f);
                float rs = rsqrtf(var + 1e-5f);
                float* oa = outA + (size_t)(b * SEQ + rbase + lane + s * 32) * 7;
                oa[0] = e0 * rs * g0 + b0;
                oa[1] = e1 * rs * g1 + b1;
                oa[2] = e2 * rs * g2 + b2;
                oa[3] = e3 * rs * g3 + b3;
                oa[4] = e4 * rs * g4 + b4;
                oa[5] = e5 * rs * g5 + b5;
                oa[6] = e6 * rs * g6 + b6;
            }
        }
    }
    __syncthreads();

    // ---- Phase B: lane owns t-quad, STG.128 coalesced weight stores ----
    if (outW) {
        const int tb = warp * 128;        // warp's 128 t-columns
        u64 pt[4][4];
#pragma unroll
        for (int j = 0; j < 4; j++) {
            const int t = tb + lane * 4 + j;
            const ulonglong2 ta = sPu[t * 2 + 0];
            const ulonglong2 tc = sPu[t * 2 + 1];
            pt[j][0] = ta.x; pt[j][1] = ta.y; pt[j][2] = tc.x; pt[j][3] = tc.y;
        }
        float* outBase = outW + ((size_t)(b * SEQ + rbase)) * SEQ + tb;

#pragma unroll 2
        for (int r = 0; r < ROWS_CTA; r++) {
            const ulonglong2 rA = sPu[(rbase + r) * 2 + 0];   // uniform loads
            const ulonglong2 rB = sPu[(rbase + r) * 2 + 1];
            const u64 lv2 = pk2(slinv[r], 0.f);
            const u64 r0 = rA.x, r1 = rA.y, r2 = rB.x, r3 = rB.y;  // pad 0
            float4 wv;
            {
                u64 z2 = fma2_(r0, pt[0][0], lv2);
                z2 = fma2_(r1, pt[0][1], z2);
                z2 = fma2_(r2, pt[0][2], z2);
                z2 = fma2_(r3, pt[0][3], z2);
                float za, zb; upk2(z2, za, zb);
                wv.x = ex2f(za + zb);
            }
            {
                u64 z2 = fma2_(r0, pt[1][0], lv2);
                z2 = fma2_(r1, pt[1][1], z2);
                z2 = fma2_(r2, pt[1][2], z2);
                z2 = fma2_(r3, pt[1][3], z2);
                float za, zb; upk2(z2, za, zb);
                wv.y = ex2f(za + zb);
            }
            {
                u64 z2 = fma2_(r0, pt[2][0], lv2);
                z2 = fma2_(r1, pt[2][1], z2);
                z2 = fma2_(r2, pt[2][2], z2);
                z2 = fma2_(r3, pt[2][3], z2);
                float za, zb; upk2(z2, za, zb);
                wv.z = ex2f(za + zb);
            }
            {
                u64 z2 = fma2_(r0, pt[3][0], lv2);
                z2 = fma2_(r1, pt[3][1], z2);
                z2 = fma2_(r2, pt[3][2], z2);
                z2 = fma2_(r3, pt[3][3], z2);
                float za, zb; upk2(z2, za, zb);
                wv.w = ex2f(za + zb);
            }
            *reinterpret_cast<float4*>(outBase + (size_t)r * SEQ + lane * 4) = wv;
        }
    }
}

extern "C" void kernel_launch(void* const* d_in, const int* in_sizes, int n_in,
                              void* d_out, int out_size) {
    const float* features = (const float*)d_in[0];
    const float* W        = (const float*)d_in[1];
    const float* bias     = (const float*)d_in[2];
    const float* abias    = (const float*)d_in[3];
    const float* gamma    = (const float*)d_in[4];
    const float* beta     = (const float*)d_in[5];

    float* out = (float*)d_out;
    const long long nA = (long long)BATCH * SEQ * DIM;       // 917504
    const long long nW = (long long)BATCH * SEQ * SEQ;       // 67108864
    float* outA = nullptr;
    float* outW = nullptr;
    long long total = (long long)out_size;
    if (total == nA + nW)      { outA = out; outW = out + nA; }
    else if (total == nW)      { outW = out; }
    else if (total == nA)      { outA = out; }
    else                       { outA = out; outW = out + nA; }

    attn_kernel<<<dim3(8, BATCH), THREADS>>>(features, W, bias, abias,
                                             gamma, beta, outA, outW);
}

// round 13
// speedup vs baseline: 1.0639x; 1.0639x over previous
#include <cuda_runtime.h>

#define BATCH 256
#define SEQ   512
#define DIM   7
#define THREADS 128
#define RPT     2            // rows per thread (phase A)
#define ROWS_CTA 128         // rows covered per CTA (quarter batch)

typedef unsigned long long u64;

// ---------- packed f32x2 helpers (Blackwell-only, PTX required) ----------
__device__ __forceinline__ u64 pk2(float a, float b) {
    u64 r;
    asm("mov.b64 %0, {%1, %2};" : "=l"(r) : "f"(a), "f"(b));
    return r;
}
__device__ __forceinline__ void upk2(u64 v, float& a, float& b) {
    asm("mov.b64 {%0, %1}, %2;" : "=f"(a), "=f"(b) : "l"(v));
}
__device__ __forceinline__ u64 fma2_(u64 a, u64 b, u64 c) {
    u64 d;
    asm("fma.rn.f32x2 %0, %1, %2, %3;" : "=l"(d) : "l"(a), "l"(b), "l"(c));
    return d;
}
__device__ __forceinline__ u64 mul2_(u64 a, u64 b) {
    u64 d;
    asm("mul.rn.f32x2 %0, %1, %2;" : "=l"(d) : "l"(a), "l"(b));
    return d;
}
__device__ __forceinline__ u64 add2_(u64 a, u64 b) {
    u64 d;
    asm("add.rn.f32x2 %0, %1, %2;" : "=l"(d) : "l"(a), "l"(b));
    return d;
}
__device__ __forceinline__ float ex2f(float x) {
    float y; asm("ex2.approx.f32 %0, %1;" : "=f"(y) : "f"(x)); return y;
}
__device__ __forceinline__ float lg2f(float x) {
    float y; asm("lg2.approx.f32 %0, %1;" : "=f"(y) : "f"(x)); return y;
}
__device__ __forceinline__ float rcpf(float x) {
    float y; asm("rcp.approx.f32 %0, %1;" : "=f"(y) : "f"(x)); return y;
}

// ---------- Single fused kernel ----------
__global__ __launch_bounds__(THREADS, 6) void attn_kernel(
    const float* __restrict__ feat,
    const float* __restrict__ Wm,
    const float* __restrict__ bia,
    const float* __restrict__ abias,
    const float* __restrict__ gamma,
    const float* __restrict__ beta,
    float* __restrict__ outA, float* __restrict__ outW) {
    __shared__ float4 sP[SEQ * 2];          // 16 KB (pre-scaled projected, pad 0)
    __shared__ float4 sV[SEQ * 2];          // 16 KB (biased values, pad 1.0 -> row sums)
    __shared__ u64    part[2][64][4];       // 4 KB  (t-half partial accumulators)
    __shared__ float  slinv[ROWS_CTA];      // -log2(rowsum)

    const int b    = blockIdx.y;
    const int quad = blockIdx.x;            // 0..3 -> which 128 rows
    const int tid  = threadIdx.x;
    const int lane = tid & 31;
    const int warp = tid >> 5;
    const int pair = warp >> 1;             // 0/1: row group within CTA
    const int th   = warp & 1;              // 0/1: t-half

    // ---- Fused prep/staging: read features, project, scale, fill smem ----
    {
        const float SC = 0.7384116545f;     // sqrt(log2(e)/sqrt(7))
        float wr[7][7], br[7], ar[7];
#pragma unroll
        for (int e = 0; e < 7; e++) {
            br[e] = __ldg(&bia[e]);
            ar[e] = __ldg(&abias[e]);
#pragma unroll
            for (int d = 0; d < 7; d++) wr[e][d] = __ldg(&Wm[e * 7 + d]);
        }
#pragma unroll
        for (int i = 0; i < 4; i++) {
            const int r = tid + i * THREADS;            // 0..511
            const float* fp = feat + ((size_t)b * SEQ + r) * 7;
            float f[7];
#pragma unroll
            for (int d = 0; d < 7; d++) f[d] = fp[d] + ar[d];
            float p[7];
#pragma unroll
            for (int e = 0; e < 7; e++) {
                float s = br[e];
#pragma unroll
                for (int d = 0; d < 7; d++) s = fmaf(f[d], wr[e][d], s);
                p[e] = s * SC;
            }
            sV[r * 2 + 0] = make_float4(f[0], f[1], f[2], f[3]);
            sV[r * 2 + 1] = make_float4(f[4], f[5], f[6], 1.0f);  // pad=1 -> sum slot
            sP[r * 2 + 0] = make_float4(p[0], p[1], p[2], p[3]);
            sP[r * 2 + 1] = make_float4(p[4], p[5], p[6], 0.f);
        }
    }
    __syncthreads();

    // Direct 64-bit pair views of the tables (LDS.128 -> f32x2 operands).
    const ulonglong2* sPu = reinterpret_cast<const ulonglong2*>(sP);
    const ulonglong2* sVu = reinterpret_cast<const ulonglong2*>(sV);

    const int rbase = quad * ROWS_CTA;                  // CTA row offset in batch
    const int rloc0 = pair * 64 + lane;                 // local row of slot 0 (s adds 32)

    u64 q[RPT][4];
#pragma unroll
    for (int s = 0; s < RPT; s++) {
        const int r = rbase + rloc0 + s * 32;
        const ulonglong2 qa = sPu[r * 2 + 0];
        const ulonglong2 qb = sPu[r * 2 + 1];
        q[s][0] = qa.x; q[s][1] = qa.y; q[s][2] = qb.x; q[s][3] = qb.y;  // pad 0
    }

    // ---- Phase A (t-half): attended accumulators; row sum rides in acc[s][3].hi ----
    u64 acc[RPT][4];
#pragma unroll
    for (int s = 0; s < RPT; s++) {
#pragma unroll
        for (int j = 0; j < 4; j++) acc[s][j] = 0ull;
    }

    const int t0 = th * 256;
#pragma unroll 8
    for (int ti = 0; ti < 256; ti++) {
        const int t = t0 + ti;
        const ulonglong2 pA = sPu[t * 2 + 0];
        const ulonglong2 pB = sPu[t * 2 + 1];
        const ulonglong2 vA = sVu[t * 2 + 0];
        const ulonglong2 vB = sVu[t * 2 + 1];   // vB.y hi = 1.0 (sum slot)
#pragma unroll
        for (int s = 0; s < RPT; s++) {
            u64 z2 = mul2_(q[s][0], pA.x);
            z2 = fma2_(q[s][1], pA.y, z2);
            z2 = fma2_(q[s][2], pB.x, z2);
            z2 = fma2_(q[s][3], pB.y, z2);
            float za, zb; upk2(z2, za, zb);
            const float e = ex2f(za + zb);
            const u64 ee = pk2(e, e);
            acc[s][0] = fma2_(ee, vA.x, acc[s][0]);
            acc[s][1] = fma2_(ee, vA.y, acc[s][1]);
            acc[s][2] = fma2_(ee, vB.x, acc[s][2]);
            acc[s][3] = fma2_(ee, vB.y, acc[s][3]);
        }
    }

    // ---- Merge t-halves: th=1 publishes, th=0 combines and finishes rows ----
    if (th == 1) {
#pragma unroll
        for (int s = 0; s < RPT; s++) {
#pragma unroll
            for (int j = 0; j < 4; j++) part[pair][s * 32 + lane][j] = acc[s][j];
        }
    }
    __syncthreads();

    if (th == 0) {
        float sum[RPT];
#pragma unroll
        for (int s = 0; s < RPT; s++) {
#pragma unroll
            for (int j = 0; j < 4; j++)
                acc[s][j] = add2_(acc[s][j], part[pair][s * 32 + lane][j]);
            float a6, sm; upk2(acc[s][3], a6, sm);
            sum[s] = sm;
            slinv[rloc0 + s * 32] = -lg2f(sm);
        }

        // ---- Attended + LayerNorm (fully per-lane) ----
        if (outA) {
            float g0 = __ldg(&gamma[0]), g1 = __ldg(&gamma[1]), g2 = __ldg(&gamma[2]),
                  g3 = __ldg(&gamma[3]), g4 = __ldg(&gamma[4]), g5 = __ldg(&gamma[5]),
                  g6 = __ldg(&gamma[6]);
            float b0 = __ldg(&beta[0]), b1 = __ldg(&beta[1]), b2 = __ldg(&beta[2]),
                  b3 = __ldg(&beta[3]), b4 = __ldg(&beta[4]), b5 = __ldg(&beta[5]),
                  b6 = __ldg(&beta[6]);
#pragma unroll
            for (int s = 0; s < RPT; s++) {
                float a0, a1, a2, a3, a4, a5, a6, ax;
                upk2(acc[s][0], a0, a1);
                upk2(acc[s][1], a2, a3);
                upk2(acc[s][2], a4, a5);
                upk2(acc[s][3], a6, ax);
                float iv = rcpf(sum[s]);
                a0 *= iv; a1 *= iv; a2 *= iv; a3 *= iv; a4 *= iv; a5 *= iv; a6 *= iv;
                float mu = (a0 + a1 + a2 + a3 + a4 + a5 + a6) * (1.0f / 7.0f);
                float e0 = a0 - mu, e1 = a1 - mu, e2 = a2 - mu, e3 = a3 - mu;
                float e4 = a4 - mu, e5 = a5 - mu, e6 = a6 - mu;
                float var = (e0*e0 + e1*e1 + e2*e2 + e3*e3 + e4*e4 + e5*e5 + e6*e6) * (1.0f / 7.0f);
                float rs = rsqrtf(var + 1e-5f);
                float* oa = outA + (size_t)(b * SEQ + rbase + rloc0 + s * 32) * 7;
                oa[0] = e0 * rs * g0 + b0;
                oa[1] = e1 * rs * g1 + b1;
                oa[2] = e2 * rs * g2 + b2;
                oa[3] = e3 * rs * g3 + b3;
                oa[4] = e4 * rs * g4 + b4;
                oa[5] = e5 * rs * g5 + b5;
                oa[6] = e6 * rs * g6 + b6;
            }
        }
    }
    __syncthreads();

    // ---- Phase B: lane owns t-quad, STG.128 coalesced weight stores ----
    if (outW) {
        const int tb = warp * 128;        // warp's 128 t-columns
        u64 pt[4][4];
#pragma unroll
        for (int j = 0; j < 4; j++) {
            const int t = tb + lane * 4 + j;
            const ulonglong2 ta = sPu[t * 2 + 0];
            const ulonglong2 tc = sPu[t * 2 + 1];
            pt[j][0] = ta.x; pt[j][1] = ta.y; pt[j][2] = tc.x; pt[j][3] = tc.y;
        }
        float* outBase = outW + ((size_t)(b * SEQ + rbase)) * SEQ + tb;

#pragma unroll 2
        for (int r = 0; r < ROWS_CTA; r++) {
            const ulonglong2 rA = sPu[(rbase + r) * 2 + 0];   // uniform loads
            const ulonglong2 rB = sPu[(rbase + r) * 2 + 1];
            const u64 lv2 = pk2(slinv[r], 0.f);
            const u64 r0 = rA.x, r1 = rA.y, r2 = rB.x, r3 = rB.y;  // pad 0
            float4 wv;
            {
                u64 z2 = fma2_(r0, pt[0][0], lv2);
                z2 = fma2_(r1, pt[0][1], z2);
                z2 = fma2_(r2, pt[0][2], z2);
                z2 = fma2_(r3, pt[0][3], z2);
                float za, zb; upk2(z2, za, zb);
                wv.x = ex2f(za + zb);
            }
            {
                u64 z2 = fma2_(r0, pt[1][0], lv2);
                z2 = fma2_(r1, pt[1][1], z2);
                z2 = fma2_(r2, pt[1][2], z2);
                z2 = fma2_(r3, pt[1][3], z2);
                float za, zb; upk2(z2, za, zb);
                wv.y = ex2f(za + zb);
            }
            {
                u64 z2 = fma2_(r0, pt[2][0], lv2);
                z2 = fma2_(r1, pt[2][1], z2);
                z2 = fma2_(r2, pt[2][2], z2);
                z2 = fma2_(r3, pt[2][3], z2);
                float za, zb; upk2(z2, za, zb);
                wv.z = ex2f(za + zb);
            }
            {
                u64 z2 = fma2_(r0, pt[3][0], lv2);
                z2 = fma2_(r1, pt[3][1], z2);
                z2 = fma2_(r2, pt[3][2], z2);
                z2 = fma2_(r3, pt[3][3], z2);
                float za, zb; upk2(z2, za, zb);
                wv.w = ex2f(za + zb);
            }
            *reinterpret_cast<float4*>(outBase + (size_t)r * SEQ + lane * 4) = wv;
        }
    }
}

extern "C" void kernel_launch(void* const* d_in, const int* in_sizes, int n_in,
                              void* d_out, int out_size) {
    const float* features = (const float*)d_in[0];
    const float* W        = (const float*)d_in[1];
    const float* bias     = (const float*)d_in[2];
    const float* abias    = (const float*)d_in[3];
    const float* gamma    = (const float*)d_in[4];
    const float* beta     = (const float*)d_in[5];

    float* out = (float*)d_out;
    const long long nA = (long long)BATCH * SEQ * DIM;       // 917504
    const long long nW = (long long)BATCH * SEQ * SEQ;       // 67108864
    float* outA = nullptr;
    float* outW = nullptr;
    long long total = (long long)out_size;
    if (total == nA + nW)      { outA = out; outW = out + nA; }
    else if (total == nW)      { outW = out; }
    else if (total == nA)      { outA = out; }
    else                       { outA = out; outW = out + nA; }

    attn_kernel<<<dim3(4, BATCH), THREADS>>>(features, W, bias, abias,
                                             gamma, beta, outA, outW);
}